// round 7
// baseline (speedup 1.0000x reference)
#include <cuda_runtime.h>
#include <cstdint>

// Problem constants
#define B_       8192
#define NROW     40
#define FDIM     256
#define NF       (NROW*FDIM)            // 10240
#define TOTROWS  (B_*NROW)              // 327680
#define TOTELEM  ((size_t)TOTROWS*FDIM) // 83,886,080
#define EPS_     1e-5f

// Fused-GEMM tiling
#define MT   160     // rows per CTA = 4 whole batches
#define NTI  128     // N tile
#define KT   16      // K tile
#define NSTG (FDIM/KT)  // 16
#define THR  320     // 10 warps

// Scratch (device-static: no allocations allowed)
__device__ float g_y[TOTELEM];      // (adj_blk @ inp) @ W
__device__ float g_Wt[FDIM*FDIM];   // W rounded to tf32
__device__ float g_sum[NF];
__device__ float g_sq[NF];
__device__ float g_scale[NF];
__device__ float g_shift[NF];

__device__ __forceinline__ float to_tf32(float x){
    float r;
    asm("cvt.rna.tf32.f32 %0, %1;" : "=f"(r) : "f"(x));
    return r;
}

__device__ __forceinline__ void cpa16(void* smem_dst, const void* gsrc){
    unsigned d = (unsigned)__cvta_generic_to_shared(smem_dst);
    asm volatile("cp.async.cg.shared.global [%0], [%1], 16;" :: "r"(d), "l"(gsrc));
}

__device__ __forceinline__ void mma_tf32(float* c, const unsigned* a, const unsigned* b){
    asm volatile(
        "mma.sync.aligned.m16n8k8.row.col.f32.tf32.tf32.f32 "
        "{%0,%1,%2,%3}, {%4,%5,%6,%7}, {%8,%9}, {%0,%1,%2,%3};\n"
        : "+f"(c[0]), "+f"(c[1]), "+f"(c[2]), "+f"(c[3])
        : "r"(a[0]), "r"(a[1]), "r"(a[2]), "r"(a[3]), "r"(b[0]), "r"(b[1]));
}

// packed f32x2 FMA (FFMA2) — PTX-only form
__device__ __forceinline__ void fma2(unsigned long long& c, unsigned long long a,
                                     unsigned long long b){
    asm("fma.rn.f32x2 %0, %1, %2, %0;" : "+l"(c) : "l"(a), "l"(b));
}
__device__ __forceinline__ unsigned long long bcast2(float a){
    unsigned long long r;
    asm("mov.b64 %0, {%1, %1};" : "=l"(r) : "f"(a));
    return r;
}
__device__ __forceinline__ float2 unpk2(unsigned long long v){
    float2 f;
    asm("mov.b64 {%0, %1}, %2;" : "=f"(f.x), "=f"(f.y) : "l"(v));
    return f;
}

// swizzled z access: sz holds z[r][k] at r*16 + (k ^ (((r>>1)&3)<<2))
__device__ __forceinline__ float zat(const float* sz, int r, int k){
    return sz[r*16 + (k ^ (((r>>1)&3)<<2))];
}

// ---------------------------------------------------------------------------
// K0: convert W to tf32, zero stat accumulators (re-zero every replay).
__global__ void k_prep(const float* __restrict__ W){
    int i = blockIdx.x * 256 + threadIdx.x;
    if (i < FDIM*FDIM) g_Wt[i] = to_tf32(W[i]);
    if (i < NF){ g_sum[i] = 0.f; g_sq[i] = 0.f; }
}

// ---------------------------------------------------------------------------
// K1: fused  Y = (adj_blk @ inp) @ W.
// CTA: 160 rows (4 batches) x 128 cols. Per K-tile: cp.async inp slab ->
// in-smem block-diag adj multiply (f32x2 FMA, tf32 round) -> mma.sync tf32.
__global__ __launch_bounds__(THR, 2) void k_fused(const float* __restrict__ inp,
                                                  const float* __restrict__ adj){
    __shared__ float sadj[16][10][10];     // 6.4 KB  (4 batches x 4 blocks)
    __shared__ float sinp[2][MT][KT];      // 20.5 KB (double-buffered raw inp)
    __shared__ float sz[MT*KT];            // 10.2 KB (tf32 z tile, XOR swizzle)
    __shared__ float sB[KT][136];          // 8.7 KB  (W tile, pad 136)

    int tid = threadIdx.x;
    int bid = blockIdx.x;
    int nb  = bid & 1;                 // pair N-CTAs adjacently -> L2 reuse of inp
    int mb  = bid >> 1;                // 0..2047
    size_t rowbase = (size_t)mb * MT;
    int n0  = nb * NTI;
    int b0  = mb * 4;                  // first batch of this CTA

    // ---- load block-diagonal adj (1600 floats) ----
    for (int i = tid; i < 1600; i += THR){
        int q  = i / 100;              // block 0..15 (batch = q/4, local p = q%4)
        int ri = (i / 10) % 10;
        int j  = i % 10;
        int b  = q >> 2, p = q & 3;
        sadj[q][ri][j] =
            adj[(size_t)(b0 + b)*(NROW*NROW) + (size_t)(p*10 + ri)*NROW + (p*10 + j)];
    }

    // warp decomposition: 10 warps = 5(m) x 2(n); warp tile 32 x 64
    int lane = tid & 31, warp = tid >> 5;
    int wm = warp >> 1, wn = warp & 1;
    int gq = lane >> 2, tq = lane & 3;

    // z-compute mapping: one row per thread, half the k-width
    int zr = tid % MT;                 // tile row 0..159
    int kh = tid / MT;                 // 0/1: k-cols kh*8..kh*8+7
    int qblk = zr / 10;                // block index 0..15
    int rloc = zr % 10;
    int srow = qblk * 10;              // tile row of block start
    int zw   = (zr >> 1) & 3;          // swizzle state for this row

    // B tile load mapping (16x128 floats = 512 float4; <=2 per thread)
    int q0 = tid, q1 = tid + THR;
    bool v1 = (q1 < 512);
    int br0 = q0 >> 5, bc0 = (q0 & 31) * 4;
    int br1 = q1 >> 5, bc1 = (q1 & 31) * 4;

    float acc[2][8][4];
    #pragma unroll
    for (int mt2 = 0; mt2 < 2; mt2++)
        #pragma unroll
        for (int nt = 0; nt < 8; nt++)
            #pragma unroll
            for (int v = 0; v < 4; v++) acc[mt2][nt][v] = 0.f;

    auto ldInp = [&](int s, int buf){
        int k0 = s * KT;
        #pragma unroll
        for (int h = 0; h < 2; h++){
            int q = tid + h*THR;       // 0..639 float4 units
            int row = q >> 2, c4 = (q & 3) * 4;
            cpa16(&sinp[buf][row][c4],
                  inp + (rowbase + row)*FDIM + k0 + c4);
        }
    };

    ldInp(0, 0);
    asm volatile("cp.async.commit_group;");

    for (int s = 0; s < NSTG; s++){
        int cur = s & 1;
        if (s + 1 < NSTG){
            ldInp(s + 1, cur ^ 1);
            asm volatile("cp.async.commit_group;");
            asm volatile("cp.async.wait_group 1;" ::: "memory");
        } else {
            asm volatile("cp.async.wait_group 0;" ::: "memory");
        }
        __syncthreads();   // sinp[cur] ready; sz & sB free (prev mma done)

        // B tile for this stage: LDG early (L2-hot), STS after z-compute
        int k0 = s * KT;
        float4 tb0 = *(const float4*)(g_Wt + (size_t)(k0 + br0)*FDIM + n0 + bc0);
        float4 tb1 = make_float4(0,0,0,0);
        if (v1) tb1 = *(const float4*)(g_Wt + (size_t)(k0 + br1)*FDIM + n0 + bc1);

        // z-compute: z[zr][kh*8 .. +7] = sum_j adj * inp, via packed f32x2
        {
            unsigned long long z0 = 0, z1 = 0, z2 = 0, z3 = 0;
            #pragma unroll
            for (int j = 0; j < 10; j++){
                const ulonglong2* xp =
                    (const ulonglong2*)&sinp[cur][srow + j][kh*8];
                ulonglong2 xa = xp[0];
                ulonglong2 xb = xp[1];
                unsigned long long ap = bcast2(sadj[qblk][rloc][j]);
                fma2(z0, ap, xa.x);
                fma2(z1, ap, xa.y);
                fma2(z2, ap, xb.x);
                fma2(z3, ap, xb.y);
            }
            float2 f0 = unpk2(z0), f1 = unpk2(z1), f2 = unpk2(z2), f3 = unpk2(z3);
            float4 lo = make_float4(to_tf32(f0.x), to_tf32(f0.y),
                                    to_tf32(f1.x), to_tf32(f1.y));
            float4 hi = make_float4(to_tf32(f2.x), to_tf32(f2.y),
                                    to_tf32(f3.x), to_tf32(f3.y));
            int u0 = kh*2;
            *(float4*)&sz[zr*16 + ((u0    ) ^ zw)*4] = lo;
            *(float4*)&sz[zr*16 + ((u0 + 1) ^ zw)*4] = hi;
        }

        // store B tile
        *(float4*)&sB[br0][bc0] = tb0;
        if (v1) *(float4*)&sB[br1][bc1] = tb1;

        __syncthreads();   // sz + sB ready

        #pragma unroll
        for (int k8 = 0; k8 < KT/8; k8++){
            int kc = k8*8 + tq;
            unsigned a[2][4];
            #pragma unroll
            for (int mt2 = 0; mt2 < 2; mt2++){
                int r0 = wm*32 + mt2*16 + gq;
                a[mt2][0] = __float_as_uint(zat(sz, r0,     kc));
                a[mt2][1] = __float_as_uint(zat(sz, r0 + 8, kc));
                a[mt2][2] = __float_as_uint(zat(sz, r0,     kc + 4));
                a[mt2][3] = __float_as_uint(zat(sz, r0 + 8, kc + 4));
            }
            #pragma unroll
            for (int nt = 0; nt < 8; nt++){
                int cc = wn*64 + nt*8 + gq;
                unsigned bb[2];
                bb[0] = __float_as_uint(sB[kc    ][cc]);
                bb[1] = __float_as_uint(sB[kc + 4][cc]);
                mma_tf32(acc[0][nt], a[0], bb);
                mma_tf32(acc[1][nt], a[1], bb);
            }
        }
        __syncthreads();   // mma done -> sz/sB reusable next iter
    }

    // Epilogue: write Y (float2 stores)
    #pragma unroll
    for (int mt2 = 0; mt2 < 2; mt2++){
        int r = wm*32 + mt2*16 + gq;
        #pragma unroll
        for (int nt = 0; nt < 8; nt++){
            int c = n0 + wn*64 + nt*8 + 2*tq;
            float2 v0 = make_float2(acc[mt2][nt][0], acc[mt2][nt][1]);
            float2 v1v = make_float2(acc[mt2][nt][2], acc[mt2][nt][3]);
            *(float2*)(g_y + (rowbase + r    )*FDIM + c) = v0;
            *(float2*)(g_y + (rowbase + r + 8)*FDIM + c) = v1v;
        }
    }
}

// ---------------------------------------------------------------------------
// K2: per-feature (r,f) sum/sumsq over the batch dim. float4 + 4-way batch
// groups for MLP, smem reduce, then 8 atomics per f4.
__global__ __launch_bounds__(256) void k_stat(){
    int r  = blockIdx.x;            // 40
    int ch = blockIdx.y;            // 32 chunks of 256 batches
    int f4 = threadIdx.x & 63;      // float4 column
    int bg = threadIdx.x >> 6;      // 0..3, 64 batches each

    const float4* p = (const float4*)g_y
        + (size_t)(ch*256 + bg*64) * (NF/4) + r*(FDIM/4) + f4;
    float4 s  = make_float4(0,0,0,0);
    float4 s2 = make_float4(0,0,0,0);
    #pragma unroll 8
    for (int b = 0; b < 64; b++){
        float4 v = p[(size_t)b * (NF/4)];
        s.x += v.x;      s.y += v.y;      s.z += v.z;      s.w += v.w;
        s2.x += v.x*v.x; s2.y += v.y*v.y; s2.z += v.z*v.z; s2.w += v.w*v.w;
    }
    __shared__ float4 rs[4][64], rq[4][64];
    rs[bg][f4] = s; rq[bg][f4] = s2;
    __syncthreads();
    if (bg == 0){
        #pragma unroll
        for (int g = 1; g < 4; g++){
            float4 a = rs[g][f4], b = rq[g][f4];
            s.x += a.x; s.y += a.y; s.z += a.z; s.w += a.w;
            s2.x += b.x; s2.y += b.y; s2.z += b.z; s2.w += b.w;
        }
        float* ps = &g_sum[r*FDIM + f4*4];
        float* pq = &g_sq [r*FDIM + f4*4];
        atomicAdd(ps+0, s.x);  atomicAdd(ps+1, s.y);
        atomicAdd(ps+2, s.z);  atomicAdd(ps+3, s.w);
        atomicAdd(pq+0, s2.x); atomicAdd(pq+1, s2.y);
        atomicAdd(pq+2, s2.z); atomicAdd(pq+3, s2.w);
    }
}

// ---------------------------------------------------------------------------
// K3: fold mean/var/gamma/beta into per-feature scale & shift.
// out = y*scale + (betaSum - mean*scale)
__global__ void k_final(const float* __restrict__ gamma,
                        const float* __restrict__ beta){
    int q = blockIdx.x * 256 + threadIdx.x;   // 0..10239
    float inv = 1.f / (float)B_;
    float mean = g_sum[q] * inv;
    float var  = g_sq[q] * inv - mean*mean;
    int i = q / (10*FDIM);                    // crop owning row r = q/256
    float sc = rsqrtf(var + EPS_) * gamma[i*NF + q];
    float bs = beta[q] + beta[NF + q] + beta[2*NF + q] + beta[3*NF + q];
    g_scale[q] = sc;
    g_shift[q] = bs - mean*sc;
}

// ---------------------------------------------------------------------------
// K4: streaming normalize (float4).
__global__ __launch_bounds__(256) void k_norm(float* __restrict__ out){
    size_t idx = (size_t)blockIdx.x * 256 + threadIdx.x;  // < 20,971,520
    int q4 = (int)(idx % (NF/4));
    float4 v  = ((const float4*)g_y)[idx];
    float4 sc = ((const float4*)g_scale)[q4];
    float4 sh = ((const float4*)g_shift)[q4];
    float4 o;
    o.x = v.x*sc.x + sh.x;
    o.y = v.y*sc.y + sh.y;
    o.z = v.z*sc.z + sh.z;
    o.w = v.w*sc.w + sh.w;
    ((float4*)out)[idx] = o;
}

// ---------------------------------------------------------------------------
extern "C" void kernel_launch(void* const* d_in, const int* in_sizes, int n_in,
                              void* d_out, int out_size){
    const float* inp   = (const float*)d_in[0];
    const float* adj   = (const float*)d_in[1];
    const float* W     = (const float*)d_in[2];
    const float* gamma = (const float*)d_in[3];
    const float* beta  = (const float*)d_in[4];
    float* out = (float*)d_out;

    k_prep <<<256, 256>>>(W);
    k_fused<<<(TOTROWS/MT)*2, THR>>>(inp, adj);
    k_stat <<<dim3(NROW, 32), 256>>>();
    k_final<<<NF/256, 256>>>(gamma, beta);
    k_norm <<<(unsigned)(TOTELEM/4/256), 256>>>(out);
}

// round 9
// speedup vs baseline: 1.1819x; 1.1819x over previous
#include <cuda_runtime.h>
#include <cstdint>

// Problem constants
#define B_       8192
#define NROW     40
#define FDIM     256
#define NF       (NROW*FDIM)            // 10240
#define TOTROWS  (B_*NROW)              // 327680
#define TOTELEM  ((size_t)TOTROWS*FDIM) // 83,886,080
#define EPS_     1e-5f

// GEMM tiling: CTA 128(M) x 128(N), KT=32, 8 stages, 256 threads
#define KT   32
#define NSTG (FDIM/KT)   // 8

// Scratch (device-static: no allocations allowed)
// g_z: fragment layout [RT=row/16][ktG=k/8][lane=g*4+t] x float4(v0,v2,v1,v3)
//   v0=z[RT*16+g][ktG*8+t], v2=z[..g][..t+4], v1=z[..8+g][..t], v3=z[..8+g][..t+4]
__device__ float g_z[TOTELEM];
__device__ float g_y[TOTELEM];          // row-major Y
// g_Wf: fragment layout [ktG=0..31][n8=0..31][lane] x float2(W[kt*8+t][n8*8+g], W[kt*8+t+4][n8*8+g])
__device__ float g_Wf[FDIM*FDIM];
__device__ float g_sum[NF];
__device__ float g_sq[NF];
__device__ float g_scale[NF];
__device__ float g_shift[NF];

__device__ __forceinline__ float to_tf32(float x){
    float r;
    asm("cvt.rna.tf32.f32 %0, %1;" : "=f"(r) : "f"(x));
    return r;
}

__device__ __forceinline__ void cpa16(void* smem_dst, const void* gsrc){
    unsigned d = (unsigned)__cvta_generic_to_shared(smem_dst);
    asm volatile("cp.async.cg.shared.global [%0], [%1], 16;" :: "r"(d), "l"(gsrc));
}

__device__ __forceinline__ void mma_tf32(float* c, const unsigned* a, const unsigned* b){
    asm volatile(
        "mma.sync.aligned.m16n8k8.row.col.f32.tf32.tf32.f32 "
        "{%0,%1,%2,%3}, {%4,%5,%6,%7}, {%8,%9}, {%0,%1,%2,%3};\n"
        : "+f"(c[0]), "+f"(c[1]), "+f"(c[2]), "+f"(c[3])
        : "r"(a[0]), "r"(a[1]), "r"(a[2]), "r"(a[3]), "r"(b[0]), "r"(b[1]));
}

// packed f32x2 FMA (FFMA2) — PTX-only
__device__ __forceinline__ void fma2(unsigned long long& c, unsigned long long a,
                                     unsigned long long b){
    asm("fma.rn.f32x2 %0, %1, %2, %0;" : "+l"(c) : "l"(a), "l"(b));
}
__device__ __forceinline__ unsigned long long bcast2(float a){
    unsigned long long r;
    asm("mov.b64 %0, {%1, %1};" : "=l"(r) : "f"(a));
    return r;
}
__device__ __forceinline__ float2 unpk2(unsigned long long v){
    float2 f;
    asm("mov.b64 {%0, %1}, %2;" : "=f"(f.x), "=f"(f.y) : "l"(v));
    return f;
}

// ---------------------------------------------------------------------------
// K0: build W fragment layout (tf32-rounded), zero stat accumulators.
__global__ void k_prep(const float* __restrict__ W){
    int i = blockIdx.x * 256 + threadIdx.x;    // 0..65535
    int lane = i & 31;
    int n8   = (i >> 5) & 31;
    int ktG  = i >> 10;
    int g = lane >> 2, t = lane & 3;
    float b0 = to_tf32(W[(ktG*8 + t    )*FDIM + n8*8 + g]);
    float b1 = to_tf32(W[(ktG*8 + t + 4)*FDIM + n8*8 + g]);
    ((float2*)g_Wf)[i] = make_float2(b0, b1);
    if (i < NF){ g_sum[i] = 0.f; g_sq[i] = 0.f; }
}

// ---------------------------------------------------------------------------
// K1: z = adj_blk @ inp, written directly in mma-fragment layout.
// Thread owns (batch, ktG, t): columns c0=ktG*8+t and c0+4, all 40 rows.
__global__ __launch_bounds__(256) void k_z(const float* __restrict__ inp,
                                           const float* __restrict__ adj){
    int b2  = blockIdx.x;            // 4096 CTAs
    int sub = threadIdx.x >> 7;      // batch within CTA
    int cp  = threadIdx.x & 127;
    int ktG = cp >> 2, t = cp & 3;
    int b   = b2*2 + sub;

    __shared__ float sadj[2][NROW][NROW];
    for (int i = threadIdx.x; i < 2*NROW*NROW; i += 256){
        int bb = i / (NROW*NROW);
        int j  = i % (NROW*NROW);
        sadj[bb][j/NROW][j%NROW] = adj[(size_t)(b2*2+bb)*NROW*NROW + j];
    }
    __syncthreads();

    int c0 = ktG*8 + t;
    // x[j] = packed (inp[b][j][c0], inp[b][j][c0+4]) — same 32B sector
    unsigned long long x[NROW];
    const float* ip = inp + (size_t)b*NROW*FDIM + c0;
    #pragma unroll
    for (int j = 0; j < NROW; j++){
        float lo = ip[j*FDIM];
        float hi = ip[j*FDIM + 4];
        asm("mov.b64 %0, {%1, %2};" : "=l"(x[j]) : "f"(lo), "f"(hi));
    }

    int growb = b * NROW;
    #pragma unroll
    for (int r = 0; r < NROW; r++){
        int s = (r/10)*10;
        unsigned long long acc = 0;
        #pragma unroll
        for (int j = 0; j < 10; j++)
            fma2(acc, bcast2(sadj[sub][r][s+j]), x[s+j]);
        float2 f = unpk2(acc);
        float2 o = make_float2(to_tf32(f.x), to_tf32(f.y));   // (v_t, v_{t+4})
        int grow = growb + r;
        int RT = grow >> 4, lr = grow & 15, g = lr & 7;
        size_t fi = (((size_t)RT*32 + ktG)*32 + (g*4 + t))*4 + ((lr >> 3) << 1);
        *(float2*)(g_z + fi) = o;
    }
}

// ---------------------------------------------------------------------------
// K2: Y = Z @ W, tf32 mma.sync with fragment-layout smem.
// A: cp.async double-buffered (32 KB). B: LDG(L2-hot)->regs prefetch -> STS,
// single buffer (16 KB). Total static smem 48 KB.
__global__ __launch_bounds__(256, 2) void k_mm(){
    __shared__ float sA[2][8*512];   // 2 x 16 KB : [buf][rt*512 + ktg*128 + lane*4 + slot]
    __shared__ float sB[4096];       // 16 KB     : [ktg*1024 + n8*64 + lane*2 + s01]

    int tid = threadIdx.x;
    int bid = blockIdx.x;
    int nb  = bid & 1;               // adjacent N-halves -> z L2 reuse
    int mb  = bid >> 1;
    int RTb = mb * 8;
    size_t rowbase = (size_t)mb * 128;
    int n0  = nb * 128;
    int lane = tid & 31, warp = tid >> 5;
    int wm = warp >> 1, wn = warp & 1;
    int gq = lane >> 2, tq = lane & 3;

    float acc[2][8][4];
    #pragma unroll
    for (int mt = 0; mt < 2; mt++)
        #pragma unroll
        for (int nt = 0; nt < 8; nt++)
            #pragma unroll
            for (int v = 0; v < 4; v++) acc[mt][nt][v] = 0.f;

    auto cpA = [&](int s, int buf){
        #pragma unroll
        for (int h = 0; h < 4; h++){
            int q  = tid + h*256;          // 0..1023 16B-units
            int rt = q >> 7;
            int u  = (q & 127) * 4;
            cpa16(&sA[buf][rt*512 + u],
                  g_z + ((size_t)(RTb + rt)*32 + s*4)*128 + u);
        }
    };
    float4 rb[4];
    auto ldB = [&](int s){
        #pragma unroll
        for (int h = 0; h < 4; h++){
            int q   = tid + h*256;         // 0..1023 16B-units of 16 KB
            int ktg = q >> 8;
            int u   = (q & 255) * 4;
            rb[h] = *(const float4*)(g_Wf + ((size_t)(s*4 + ktg)*32 + nb*16)*64 + u);
        }
    };
    auto stB = [&](){
        #pragma unroll
        for (int h = 0; h < 4; h++){
            int q = tid + h*256;
            int ktg = q >> 8;
            int u   = (q & 255) * 4;
            *(float4*)&sB[ktg*1024 + u] = rb[h];
        }
    };

    ldB(0);
    cpA(0, 0);
    asm volatile("cp.async.commit_group;");

    for (int s = 0; s < NSTG; s++){
        int cur = s & 1;
        asm volatile("cp.async.wait_group 0;" ::: "memory");
        __syncthreads();                 // A(cur) in; everyone done w/ prev mma
        stB();
        if (s + 1 < NSTG){
            cpA(s + 1, cur ^ 1);
            asm volatile("cp.async.commit_group;");
        }
        __syncthreads();                 // sB visible
        if (s + 1 < NSTG) ldB(s + 1);    // prefetch next B under mma

        #pragma unroll
        for (int k8 = 0; k8 < 4; k8++){
            unsigned a[2][4];
            #pragma unroll
            for (int mt = 0; mt < 2; mt++){
                int rt = wm*2 + mt;
                float4 fa = *(const float4*)&sA[cur][rt*512 + k8*128 + lane*4];
                a[mt][0] = __float_as_uint(fa.x);   // v0
                a[mt][1] = __float_as_uint(fa.z);   // v1
                a[mt][2] = __float_as_uint(fa.y);   // v2
                a[mt][3] = __float_as_uint(fa.w);   // v3
            }
            #pragma unroll
            for (int nt = 0; nt < 8; nt++){
                float2 fb = *(const float2*)&sB[(k8*16 + wn*8 + nt)*64 + lane*2];
                unsigned bb[2] = { __float_as_uint(fb.x), __float_as_uint(fb.y) };
                mma_tf32(acc[0][nt], a[0], bb);
                mma_tf32(acc[1][nt], a[1], bb);
            }
        }
    }

    // Epilogue: write Y row-major (float2)
    #pragma unroll
    for (int mt = 0; mt < 2; mt++){
        int r = wm*32 + mt*16 + gq;
        #pragma unroll
        for (int nt = 0; nt < 8; nt++){
            int c = n0 + wn*64 + nt*8 + 2*tq;
            float2 v0 = make_float2(acc[mt][nt][0], acc[mt][nt][1]);
            float2 v1 = make_float2(acc[mt][nt][2], acc[mt][nt][3]);
            *(float2*)(g_y + (rowbase + r    )*FDIM + c) = v0;
            *(float2*)(g_y + (rowbase + r + 8)*FDIM + c) = v1;
        }
    }
}

// ---------------------------------------------------------------------------
// K3: per-feature (r,f) sum/sumsq over batch. float4 + 4 batch groups.
__global__ __launch_bounds__(256) void k_stat(){
    int r  = blockIdx.x;            // 40
    int ch = blockIdx.y;            // 32 chunks of 256 batches
    int f4 = threadIdx.x & 63;
    int bg = threadIdx.x >> 6;

    const float4* p = (const float4*)g_y
        + (size_t)(ch*256 + bg*64) * (NF/4) + r*(FDIM/4) + f4;
    float4 s  = make_float4(0,0,0,0);
    float4 s2 = make_float4(0,0,0,0);
    #pragma unroll 8
    for (int b = 0; b < 64; b++){
        float4 v = p[(size_t)b * (NF/4)];
        s.x += v.x;      s.y += v.y;      s.z += v.z;      s.w += v.w;
        s2.x += v.x*v.x; s2.y += v.y*v.y; s2.z += v.z*v.z; s2.w += v.w*v.w;
    }
    __shared__ float4 rs[4][64], rq[4][64];
    rs[bg][f4] = s; rq[bg][f4] = s2;
    __syncthreads();
    if (bg == 0){
        #pragma unroll
        for (int g = 1; g < 4; g++){
            float4 a = rs[g][f4], b = rq[g][f4];
            s.x += a.x; s.y += a.y; s.z += a.z; s.w += a.w;
            s2.x += b.x; s2.y += b.y; s2.z += b.z; s2.w += b.w;
        }
        float* ps = &g_sum[r*FDIM + f4*4];
        float* pq = &g_sq [r*FDIM + f4*4];
        atomicAdd(ps+0, s.x);  atomicAdd(ps+1, s.y);
        atomicAdd(ps+2, s.z);  atomicAdd(ps+3, s.w);
        atomicAdd(pq+0, s2.x); atomicAdd(pq+1, s2.y);
        atomicAdd(pq+2, s2.z); atomicAdd(pq+3, s2.w);
    }
}

// ---------------------------------------------------------------------------
// K4: fold mean/var/gamma/beta -> per-feature scale & shift.
__global__ void k_final(const float* __restrict__ gamma,
                        const float* __restrict__ beta){
    int q = blockIdx.x * 256 + threadIdx.x;   // 0..10239
    float inv = 1.f / (float)B_;
    float mean = g_sum[q] * inv;
    float var  = g_sq[q] * inv - mean*mean;
    int i = q / (10*FDIM);
    float sc = rsqrtf(var + EPS_) * gamma[i*NF + q];
    float bs = beta[q] + beta[NF + q] + beta[2*NF + q] + beta[3*NF + q];
    g_scale[q] = sc;
    g_shift[q] = bs - mean*sc;
}

// ---------------------------------------------------------------------------
// K5: streaming normalize (float4).
__global__ __launch_bounds__(256) void k_norm(float* __restrict__ out){
    size_t idx = (size_t)blockIdx.x * 256 + threadIdx.x;
    int q4 = (int)(idx % (NF/4));
    float4 v  = ((const float4*)g_y)[idx];
    float4 sc = ((const float4*)g_scale)[q4];
    float4 sh = ((const float4*)g_shift)[q4];
    float4 o;
    o.x = v.x*sc.x + sh.x;
    o.y = v.y*sc.y + sh.y;
    o.z = v.z*sc.z + sh.z;
    o.w = v.w*sc.w + sh.w;
    ((float4*)out)[idx] = o;
}

// ---------------------------------------------------------------------------
extern "C" void kernel_launch(void* const* d_in, const int* in_sizes, int n_in,
                              void* d_out, int out_size){
    const float* inp   = (const float*)d_in[0];
    const float* adj   = (const float*)d_in[1];
    const float* W     = (const float*)d_in[2];
    const float* gamma = (const float*)d_in[3];
    const float* beta  = (const float*)d_in[4];
    float* out = (float*)d_out;

    k_prep <<<256, 256>>>(W);
    k_z    <<<B_/2, 256>>>(inp, adj);
    k_mm   <<<(TOTROWS/128)*2, 256>>>();
    k_stat <<<dim3(NROW, 32), 256>>>();
    k_final<<<NF/256, 256>>>(gamma, beta);
    k_norm <<<(unsigned)(TOTELEM/4/256), 256>>>(out);
}